// round 2
// baseline (speedup 1.0000x reference)
#include <cuda_runtime.h>
#include <cuda_bf16.h>
#include <cstdint>

// ---------------------------------------------------------------------------
// B=16, C=512, S=1024, HEAD=8, D_K=64
// heads view: token n -> channel n>>1, feature j=h*64+d -> spatial ((n&1)<<9)+j
// 3xTF32 compensated precision: x = hi + lo, A*B ~= Ah*Bh + Al*Bh + Ah*Bl
// ---------------------------------------------------------------------------
#define BATCH   16
#define CH      512
#define SP      1024
#define NHEAD   8
#define PER_B   (CH*SP)

__device__ float g_q[BATCH*PER_B];
__device__ float g_k[BATCH*PER_B];
__device__ float g_v[BATCH*PER_B];
__device__ float g_att[BATCH*PER_B];
__device__ float g_o1[BATCH*PER_B];

__device__ __forceinline__ unsigned f2tf(float x) {
    unsigned u;
    asm("cvt.rna.tf32.f32 %0, %1;" : "=r"(u) : "f"(x));
    return u;
}
__device__ __forceinline__ void split_tf(float x, unsigned& hi, unsigned& lo) {
    hi = f2tf(x);
    lo = f2tf(x - __uint_as_float(hi));
}
__device__ __forceinline__ void mma8(float* c, const unsigned* a, unsigned b0, unsigned b1) {
    asm volatile(
        "mma.sync.aligned.m16n8k8.row.col.f32.tf32.tf32.f32 "
        "{%0,%1,%2,%3},{%4,%5,%6,%7},{%8,%9},{%0,%1,%2,%3};"
        : "+f"(c[0]), "+f"(c[1]), "+f"(c[2]), "+f"(c[3])
        : "r"(a[0]), "r"(a[1]), "r"(a[2]), "r"(a[3]), "r"(b0), "r"(b1));
}

// ---------------------------------------------------------------------------
// GEMM: Y[b] = W[512x512] @ X[b][512x1024] + bias, 3xTF32.
// grid (8, 4, 16), 256 thr. Warp grid 4(m) x 2(n); warp tile 32x64.
// dyn smem: Ah/Al[128][36] + Bh/Bl[32][132] = 70656 B
// ---------------------------------------------------------------------------
#define GEMM_SMEM ((2*128*36 + 2*32*132) * 4)

__global__ __launch_bounds__(256, 2)
void gemm512_kernel(const float* __restrict__ W, const float* __restrict__ bias,
                    const float* __restrict__ X, float* __restrict__ Y)
{
    extern __shared__ unsigned gsm[];
    unsigned (*Ah)[36]  = reinterpret_cast<unsigned(*)[36]>(gsm);
    unsigned (*Al)[36]  = reinterpret_cast<unsigned(*)[36]>(gsm + 128*36);
    unsigned (*Bh)[132] = reinterpret_cast<unsigned(*)[132]>(gsm + 2*128*36);
    unsigned (*Bl)[132] = reinterpret_cast<unsigned(*)[132]>(gsm + 2*128*36 + 32*132);

    const int b  = blockIdx.z;
    const float* Xb = X + (size_t)b * PER_B;
    float*       Yb = Y + (size_t)b * PER_B;
    const int m0 = blockIdx.y * 128;
    const int n0 = blockIdx.x * 128;
    const int tid = threadIdx.x, lane = tid & 31, warp = tid >> 5;
    const int wm = warp & 3, wn = warp >> 2;
    const int g = lane >> 2, tg = lane & 3;

    float acc[2][8][4];
#pragma unroll
    for (int mt = 0; mt < 2; mt++)
#pragma unroll
        for (int nt = 0; nt < 8; nt++)
#pragma unroll
            for (int i = 0; i < 4; i++) acc[mt][nt][i] = 0.f;

    for (int k0 = 0; k0 < 512; k0 += 32) {
#pragma unroll
        for (int i = 0; i < 4; i++) {
            int f = tid + i * 256;
            int r = f >> 3, c = (f & 7) << 2;
            float4 v = *reinterpret_cast<const float4*>(W + (size_t)(m0 + r) * 512 + k0 + c);
            split_tf(v.x, Ah[r][c],     Al[r][c]);
            split_tf(v.y, Ah[r][c + 1], Al[r][c + 1]);
            split_tf(v.z, Ah[r][c + 2], Al[r][c + 2]);
            split_tf(v.w, Ah[r][c + 3], Al[r][c + 3]);
        }
#pragma unroll
        for (int i = 0; i < 4; i++) {
            int f = tid + i * 256;
            int r = f >> 5, c = (f & 31) << 2;
            float4 v = *reinterpret_cast<const float4*>(Xb + (size_t)(k0 + r) * SP + n0 + c);
            split_tf(v.x, Bh[r][c],     Bl[r][c]);
            split_tf(v.y, Bh[r][c + 1], Bl[r][c + 1]);
            split_tf(v.z, Bh[r][c + 2], Bl[r][c + 2]);
            split_tf(v.w, Bh[r][c + 3], Bl[r][c + 3]);
        }
        __syncthreads();

#pragma unroll
        for (int ks = 0; ks < 4; ks++) {
            const int kk = ks << 3;
            unsigned ah[2][4], al[2][4];
#pragma unroll
            for (int mt = 0; mt < 2; mt++) {
                int rm = wm * 32 + mt * 16;
                ah[mt][0] = Ah[rm + g][kk + tg];
                ah[mt][1] = Ah[rm + g + 8][kk + tg];
                ah[mt][2] = Ah[rm + g][kk + tg + 4];
                ah[mt][3] = Ah[rm + g + 8][kk + tg + 4];
                al[mt][0] = Al[rm + g][kk + tg];
                al[mt][1] = Al[rm + g + 8][kk + tg];
                al[mt][2] = Al[rm + g][kk + tg + 4];
                al[mt][3] = Al[rm + g + 8][kk + tg + 4];
            }
#pragma unroll
            for (int nt = 0; nt < 8; nt++) {
                int cn = wn * 64 + nt * 8;
                unsigned bh0 = Bh[kk + tg][cn + g];
                unsigned bh1 = Bh[kk + tg + 4][cn + g];
                unsigned bl0 = Bl[kk + tg][cn + g];
                unsigned bl1 = Bl[kk + tg + 4][cn + g];
#pragma unroll
                for (int mt = 0; mt < 2; mt++) {
                    mma8(acc[mt][nt], ah[mt], bh0, bh1);
                    mma8(acc[mt][nt], al[mt], bh0, bh1);
                    mma8(acc[mt][nt], ah[mt], bl0, bl1);
                }
            }
        }
        __syncthreads();
    }

#pragma unroll
    for (int mt = 0; mt < 2; mt++) {
        int r0 = m0 + wm * 32 + mt * 16 + g;
        float bi0 = bias[r0], bi1 = bias[r0 + 8];
#pragma unroll
        for (int nt = 0; nt < 8; nt++) {
            int cn = n0 + wn * 64 + nt * 8 + 2 * tg;
            Yb[(size_t)r0 * SP + cn]           = acc[mt][nt][0] + bi0;
            Yb[(size_t)r0 * SP + cn + 1]       = acc[mt][nt][1] + bi0;
            Yb[(size_t)(r0 + 8) * SP + cn]     = acc[mt][nt][2] + bi1;
            Yb[(size_t)(r0 + 8) * SP + cn + 1] = acc[mt][nt][3] + bi1;
        }
    }
}

// ---------------------------------------------------------------------------
// Attention per (b,h): Q,K,V are [1024,64] strided views. 3xTF32 both matmuls.
// P re-layout C-frag -> A-frag via quad shuffles (no smem round-trip).
// grid (8, 8, 16), 256 thr. dyn smem: Kh/Kl/Vh/Vl[128][68] = 139264 B
// ---------------------------------------------------------------------------
#define ATTN_SMEM (4*128*68*4)

__device__ __forceinline__ size_t tok_off(int n, int hoff) {
    return (size_t)(n >> 1) * SP + ((n & 1) << 9) + hoff;
}

__global__ __launch_bounds__(256, 1)
void attn_kernel(const float* __restrict__ Q, const float* __restrict__ K,
                 const float* __restrict__ V, float* __restrict__ O)
{
    extern __shared__ unsigned smem_u[];
    unsigned (*Kh)[68] = reinterpret_cast<unsigned(*)[68]>(smem_u);
    unsigned (*Kl)[68] = reinterpret_cast<unsigned(*)[68]>(smem_u + 128*68);
    unsigned (*Vh)[68] = reinterpret_cast<unsigned(*)[68]>(smem_u + 2*128*68);
    unsigned (*Vl)[68] = reinterpret_cast<unsigned(*)[68]>(smem_u + 3*128*68);

    const int tid = threadIdx.x, lane = tid & 31, warp = tid >> 5;
    const int g = lane >> 2, tg = lane & 3;
    const unsigned srcA = (lane & ~3) | (tg >> 1);        // col tg owner
    const unsigned srcB = (lane & ~3) | (2 + (tg >> 1));  // col tg+4 owner
    const bool odd = (tg & 1);

    const int b = blockIdx.z, h = blockIdx.y;
    const int n0 = blockIdx.x * 128;
    const size_t bb = (size_t)b * PER_B;
    const int hoff = h * 64;

    // Q fragments (rows warp*16+g, +8), pre-scaled by 1/8, hi/lo split
    const int r0l = warp * 16 + g, r1l = r0l + 8;
    const float* q0 = Q + bb + tok_off(n0 + r0l, hoff);
    const float* q1 = Q + bb + tok_off(n0 + r1l, hoff);
    unsigned qh[8][4], ql[8][4];
#pragma unroll
    for (int ks = 0; ks < 8; ks++) {
        split_tf(q0[ks * 8 + tg]     * 0.125f, qh[ks][0], ql[ks][0]);
        split_tf(q1[ks * 8 + tg]     * 0.125f, qh[ks][1], ql[ks][1]);
        split_tf(q0[ks * 8 + tg + 4] * 0.125f, qh[ks][2], ql[ks][2]);
        split_tf(q1[ks * 8 + tg + 4] * 0.125f, qh[ks][3], ql[ks][3]);
    }

    float mr0 = -1e30f, mr1 = -1e30f, l0 = 0.f, l1 = 0.f;
    float oa[8][4];
#pragma unroll
    for (int dt = 0; dt < 8; dt++)
#pragma unroll
        for (int i = 0; i < 4; i++) oa[dt][i] = 0.f;

    for (int kb = 0; kb < 8; kb++) {
#pragma unroll
        for (int i = 0; i < 8; i++) {
            int f = tid + i * 256;
            int r = f >> 4, c = (f & 15) << 2;
            size_t off = bb + tok_off(kb * 128 + r, hoff) + c;
            float4 kv = *reinterpret_cast<const float4*>(K + off);
            split_tf(kv.x, Kh[r][c],     Kl[r][c]);
            split_tf(kv.y, Kh[r][c + 1], Kl[r][c + 1]);
            split_tf(kv.z, Kh[r][c + 2], Kl[r][c + 2]);
            split_tf(kv.w, Kh[r][c + 3], Kl[r][c + 3]);
            float4 vv = *reinterpret_cast<const float4*>(V + off);
            split_tf(vv.x, Vh[r][c],     Vl[r][c]);
            split_tf(vv.y, Vh[r][c + 1], Vl[r][c + 1]);
            split_tf(vv.z, Vh[r][c + 2], Vl[r][c + 2]);
            split_tf(vv.w, Vh[r][c + 3], Vl[r][c + 3]);
        }
        __syncthreads();

        // S = Q K^T (16 rows x 128 cols per warp), 3xTF32
        float sc[16][4];
#pragma unroll
        for (int nt = 0; nt < 16; nt++) {
            sc[nt][0] = sc[nt][1] = sc[nt][2] = sc[nt][3] = 0.f;
#pragma unroll
            for (int ks = 0; ks < 8; ks++) {
                unsigned bh0 = Kh[nt * 8 + g][ks * 8 + tg];
                unsigned bh1 = Kh[nt * 8 + g][ks * 8 + tg + 4];
                unsigned bl0 = Kl[nt * 8 + g][ks * 8 + tg];
                unsigned bl1 = Kl[nt * 8 + g][ks * 8 + tg + 4];
                mma8(sc[nt], qh[ks], bh0, bh1);
                mma8(sc[nt], ql[ks], bh0, bh1);
                mma8(sc[nt], qh[ks], bl0, bl1);
            }
        }

        // online softmax
        float mx0 = -1e30f, mx1 = -1e30f;
#pragma unroll
        for (int nt = 0; nt < 16; nt++) {
            mx0 = fmaxf(mx0, fmaxf(sc[nt][0], sc[nt][1]));
            mx1 = fmaxf(mx1, fmaxf(sc[nt][2], sc[nt][3]));
        }
        mx0 = fmaxf(mx0, __shfl_xor_sync(0xffffffff, mx0, 1));
        mx0 = fmaxf(mx0, __shfl_xor_sync(0xffffffff, mx0, 2));
        mx1 = fmaxf(mx1, __shfl_xor_sync(0xffffffff, mx1, 1));
        mx1 = fmaxf(mx1, __shfl_xor_sync(0xffffffff, mx1, 2));
        float mn0 = fmaxf(mr0, mx0), mn1 = fmaxf(mr1, mx1);
        float al0 = __expf(mr0 - mn0), al1 = __expf(mr1 - mn1);
        float ps0 = 0.f, ps1 = 0.f;
#pragma unroll
        for (int nt = 0; nt < 16; nt++) {
            sc[nt][0] = __expf(sc[nt][0] - mn0);
            sc[nt][1] = __expf(sc[nt][1] - mn0);
            sc[nt][2] = __expf(sc[nt][2] - mn1);
            sc[nt][3] = __expf(sc[nt][3] - mn1);
            ps0 += sc[nt][0] + sc[nt][1];
            ps1 += sc[nt][2] + sc[nt][3];
        }
        ps0 += __shfl_xor_sync(0xffffffff, ps0, 1);
        ps0 += __shfl_xor_sync(0xffffffff, ps0, 2);
        ps1 += __shfl_xor_sync(0xffffffff, ps1, 1);
        ps1 += __shfl_xor_sync(0xffffffff, ps1, 2);
        l0 = l0 * al0 + ps0;
        l1 = l1 * al1 + ps1;
        mr0 = mn0; mr1 = mn1;
#pragma unroll
        for (int dt = 0; dt < 8; dt++) {
            oa[dt][0] *= al0; oa[dt][1] *= al0;
            oa[dt][2] *= al1; oa[dt][3] *= al1;
        }

        // O += P V : per 8-col chunk, re-layout P via quad shuffles, split, 3 mmas
#pragma unroll
        for (int nt = 0; nt < 16; nt++) {
            float v0a = __shfl_sync(0xffffffff, sc[nt][0], srcA);
            float v1a = __shfl_sync(0xffffffff, sc[nt][1], srcA);
            float v2a = __shfl_sync(0xffffffff, sc[nt][2], srcA);
            float v3a = __shfl_sync(0xffffffff, sc[nt][3], srcA);
            float v0b = __shfl_sync(0xffffffff, sc[nt][0], srcB);
            float v1b = __shfl_sync(0xffffffff, sc[nt][1], srcB);
            float v2b = __shfl_sync(0xffffffff, sc[nt][2], srcB);
            float v3b = __shfl_sync(0xffffffff, sc[nt][3], srcB);
            float p0 = odd ? v1a : v0a;   // P(g,    tg)
            float p1 = odd ? v3a : v2a;   // P(g+8,  tg)
            float p2 = odd ? v1b : v0b;   // P(g,    tg+4)
            float p3 = odd ? v3b : v2b;   // P(g+8,  tg+4)
            unsigned ah[4], al[4];
            split_tf(p0, ah[0], al[0]);
            split_tf(p1, ah[1], al[1]);
            split_tf(p2, ah[2], al[2]);
            split_tf(p3, ah[3], al[3]);
#pragma unroll
            for (int dt = 0; dt < 8; dt++) {
                unsigned vh0 = Vh[nt * 8 + tg][dt * 8 + g];
                unsigned vh1 = Vh[nt * 8 + tg + 4][dt * 8 + g];
                unsigned vl0 = Vl[nt * 8 + tg][dt * 8 + g];
                unsigned vl1 = Vl[nt * 8 + tg + 4][dt * 8 + g];
                mma8(oa[dt], ah, vh0, vh1);
                mma8(oa[dt], al, vh0, vh1);
                mma8(oa[dt], ah, vl0, vl1);
            }
        }
        __syncthreads();
    }

    const float inv0 = 1.f / l0, inv1 = 1.f / l1;

    // transpose O through smem for coalesced image store
    float (*Os)[68] = reinterpret_cast<float(*)[68]>(smem_u);
#pragma unroll
    for (int dt = 0; dt < 8; dt++) {
        Os[r0l][dt * 8 + 2 * tg]     = oa[dt][0] * inv0;
        Os[r0l][dt * 8 + 2 * tg + 1] = oa[dt][1] * inv0;
        Os[r1l][dt * 8 + 2 * tg]     = oa[dt][2] * inv1;
        Os[r1l][dt * 8 + 2 * tg + 1] = oa[dt][3] * inv1;
    }
    __syncthreads();
    for (int idx = tid; idx < 64 * 128; idx += 256) {
        int j = idx >> 7, nl = idx & 127;
        O[bb + (size_t)(hoff + j) * SP + n0 + nl] = Os[nl][j];
    }
}

// ---------------------------------------------------------------------------
// InstanceNorm per (b,c) row, in-place. biased var, eps=1e-5
// ---------------------------------------------------------------------------
__global__ __launch_bounds__(256)
void inorm_kernel(float* __restrict__ Y)
{
    float* p = Y + (size_t)blockIdx.x * SP;
    const int tid = threadIdx.x, lane = tid & 31, warp = tid >> 5;
    float4 v = reinterpret_cast<const float4*>(p)[tid];
    float s = v.x + v.y + v.z + v.w;
    float q = v.x * v.x + v.y * v.y + v.z * v.z + v.w * v.w;
#pragma unroll
    for (int off = 16; off > 0; off >>= 1) {
        s += __shfl_xor_sync(0xffffffff, s, off);
        q += __shfl_xor_sync(0xffffffff, q, off);
    }
    __shared__ float ss[8], sq[8];
    if (lane == 0) { ss[warp] = s; sq[warp] = q; }
    __syncthreads();
    __shared__ float fmean, finv;
    if (tid == 0) {
        float S = 0.f, Qs = 0.f;
#pragma unroll
        for (int i = 0; i < 8; i++) { S += ss[i]; Qs += sq[i]; }
        float mean = S * (1.f / SP);
        float var = Qs * (1.f / SP) - mean * mean;
        fmean = mean;
        finv = rsqrtf(var + 1e-5f);
    }
    __syncthreads();
    float mean = fmean, inv = finv;
    v.x = (v.x - mean) * inv;
    v.y = (v.y - mean) * inv;
    v.z = (v.z - mean) * inv;
    v.w = (v.w - mean) * inv;
    reinterpret_cast<float4*>(p)[tid] = v;
}

// ---------------------------------------------------------------------------
extern "C" void kernel_launch(void* const* d_in, const int* in_sizes, int n_in,
                              void* d_out, int out_size)
{
    const float* x  = (const float*)d_in[0];
    const float* Wq = (const float*)d_in[1];
    const float* bq = (const float*)d_in[2];
    const float* Wk = (const float*)d_in[3];
    const float* bk = (const float*)d_in[4];
    const float* Wv = (const float*)d_in[5];
    const float* bv = (const float*)d_in[6];
    const float* Wo = (const float*)d_in[7];
    const float* bo = (const float*)d_in[8];

    float *gq, *gk, *gv, *gatt, *go1;
    cudaGetSymbolAddress((void**)&gq, g_q);
    cudaGetSymbolAddress((void**)&gk, g_k);
    cudaGetSymbolAddress((void**)&gv, g_v);
    cudaGetSymbolAddress((void**)&gatt, g_att);
    cudaGetSymbolAddress((void**)&go1, g_o1);

    cudaFuncSetAttribute(gemm512_kernel, cudaFuncAttributeMaxDynamicSharedMemorySize, GEMM_SMEM);
    cudaFuncSetAttribute(attn_kernel,    cudaFuncAttributeMaxDynamicSharedMemorySize, ATTN_SMEM);

    dim3 gg(8, 4, BATCH), bt(256);
    gemm512_kernel<<<gg, bt, GEMM_SMEM>>>(Wq, bq, x, gq);
    gemm512_kernel<<<gg, bt, GEMM_SMEM>>>(Wk, bk, x, gk);
    gemm512_kernel<<<gg, bt, GEMM_SMEM>>>(Wv, bv, x, gv);

    attn_kernel<<<dim3(8, NHEAD, BATCH), bt, ATTN_SMEM>>>(gq, gk, gv, gatt);

    gemm512_kernel<<<gg, bt, GEMM_SMEM>>>(Wo, bo, gatt, go1);
    inorm_kernel<<<BATCH * CH, 256>>>(go1);
    gemm512_kernel<<<gg, bt, GEMM_SMEM>>>(Wo, bo, go1, (float*)d_out);
}

// round 4
// speedup vs baseline: 1.6927x; 1.6927x over previous
#include <cuda_runtime.h>
#include <cuda_bf16.h>
#include <cstdint>

// ---------------------------------------------------------------------------
// B=16, C=512, S=1024, HEAD=8, D_K=64
// heads view: token n -> channel n>>1, feature j=h*64+d -> spatial ((n&1)<<9)+j
// 3xBF16 compensated: x = hi + lo (bf16 each), A*B ~= Ah*Bh + Al*Bh + Ah*Bl
// All MMAs: mma.sync.aligned.m16n8k16.row.col.f32.bf16.bf16.f32
// ---------------------------------------------------------------------------
#define BATCH   16
#define CH      512
#define SP      1024
#define NHEAD   8
#define PER_B   (CH*SP)

__device__ float g_q[BATCH*PER_B];
__device__ float g_k[BATCH*PER_B];
__device__ float g_v[BATCH*PER_B];
__device__ float g_att[BATCH*PER_B];
__device__ float g_o1[BATCH*PER_B];

// pack two floats to bf16x2: low16 = a, high16 = b
__device__ __forceinline__ unsigned packbf(float a, float b) {
    unsigned r;
    asm("cvt.rn.bf16x2.f32 %0, %1, %2;" : "=r"(r) : "f"(b), "f"(a));
    return r;
}
// hi/lo split of a pair
__device__ __forceinline__ void split2(float a, float b, unsigned& hi, unsigned& lo) {
    hi = packbf(a, b);
    float ha = __uint_as_float(hi << 16);
    float hb = __uint_as_float(hi & 0xffff0000u);
    lo = packbf(a - ha, b - hb);
}
__device__ __forceinline__ void mma16(float* c, const unsigned* a, unsigned b0, unsigned b1) {
    asm volatile(
        "mma.sync.aligned.m16n8k16.row.col.f32.bf16.bf16.f32 "
        "{%0,%1,%2,%3},{%4,%5,%6,%7},{%8,%9},{%0,%1,%2,%3};"
        : "+f"(c[0]), "+f"(c[1]), "+f"(c[2]), "+f"(c[3])
        : "r"(a[0]), "r"(a[1]), "r"(a[2]), "r"(a[3]), "r"(b0), "r"(b1));
}

// ---------------------------------------------------------------------------
// GEMM: Y[b] = W[512x512] @ X[b][512x1024] + bias, 3xBF16.
// grid (8,4,16), 256 thr. Warp grid 4(m) x 2(n); warp tile 32x64.
// smem (pairs, bf16x2): Ah/Al[128][20], Bh/Bl[16][132]  = 37376 B
// ---------------------------------------------------------------------------
#define GEMM_SMEM ((2*128*20 + 2*16*132) * 4)

__global__ __launch_bounds__(256, 2)
void gemm512_kernel(const float* __restrict__ W, const float* __restrict__ bias,
                    const float* __restrict__ X, float* __restrict__ Y)
{
    extern __shared__ unsigned gsm[];
    unsigned (*Ahp)[20]  = reinterpret_cast<unsigned(*)[20]>(gsm);
    unsigned (*Alp)[20]  = reinterpret_cast<unsigned(*)[20]>(gsm + 128*20);
    unsigned (*Bph)[132] = reinterpret_cast<unsigned(*)[132]>(gsm + 2*128*20);
    unsigned (*Bpl)[132] = reinterpret_cast<unsigned(*)[132]>(gsm + 2*128*20 + 16*132);

    const int b  = blockIdx.z;
    const float* Xb = X + (size_t)b * PER_B;
    float*       Yb = Y + (size_t)b * PER_B;
    const int m0 = blockIdx.y * 128;
    const int n0 = blockIdx.x * 128;
    const int tid = threadIdx.x, lane = tid & 31, warp = tid >> 5;
    const int wm = warp & 3, wn = warp >> 2;
    const int g = lane >> 2, tg = lane & 3;

    float acc[2][8][4];
#pragma unroll
    for (int mt = 0; mt < 2; mt++)
#pragma unroll
        for (int nt = 0; nt < 8; nt++)
#pragma unroll
            for (int i = 0; i < 4; i++) acc[mt][nt][i] = 0.f;

    for (int k0 = 0; k0 < 512; k0 += 32) {
        // A tile: W[m0..+127][k0..+31], pack pairs along k
#pragma unroll
        for (int i = 0; i < 4; i++) {
            int f = tid + i * 256;
            int r = f >> 3, c = (f & 7) << 2;
            float4 v = *reinterpret_cast<const float4*>(W + (size_t)(m0 + r) * 512 + k0 + c);
            split2(v.x, v.y, Ahp[r][c >> 1],       Alp[r][c >> 1]);
            split2(v.z, v.w, Ahp[r][(c >> 1) + 1], Alp[r][(c >> 1) + 1]);
        }
        // B tile: X[k0..+31][n0..+127], pack pairs along k (two rows)
#pragma unroll
        for (int i = 0; i < 2; i++) {
            int idx = tid + i * 256;
            int pr = idx >> 5, c = (idx & 31) << 2;
            const float* base = Xb + (size_t)(k0 + 2 * pr) * SP + n0 + c;
            float4 r0 = *reinterpret_cast<const float4*>(base);
            float4 r1 = *reinterpret_cast<const float4*>(base + SP);
            split2(r0.x, r1.x, Bph[pr][c],     Bpl[pr][c]);
            split2(r0.y, r1.y, Bph[pr][c + 1], Bpl[pr][c + 1]);
            split2(r0.z, r1.z, Bph[pr][c + 2], Bpl[pr][c + 2]);
            split2(r0.w, r1.w, Bph[pr][c + 3], Bpl[pr][c + 3]);
        }
        __syncthreads();

#pragma unroll
        for (int kc = 0; kc < 2; kc++) {
            const int base = kc * 8;
            unsigned ah[2][4], al[2][4];
#pragma unroll
            for (int mt = 0; mt < 2; mt++) {
                int rm = wm * 32 + mt * 16;
                ah[mt][0] = Ahp[rm + g][base + tg];
                ah[mt][1] = Ahp[rm + g + 8][base + tg];
                ah[mt][2] = Ahp[rm + g][base + tg + 4];
                ah[mt][3] = Ahp[rm + g + 8][base + tg + 4];
                al[mt][0] = Alp[rm + g][base + tg];
                al[mt][1] = Alp[rm + g + 8][base + tg];
                al[mt][2] = Alp[rm + g][base + tg + 4];
                al[mt][3] = Alp[rm + g + 8][base + tg + 4];
            }
#pragma unroll
            for (int nt = 0; nt < 8; nt++) {
                int cn = wn * 64 + nt * 8;
                unsigned bh0 = Bph[base + tg][cn + g];
                unsigned bh1 = Bph[base + tg + 4][cn + g];
                unsigned bl0 = Bpl[base + tg][cn + g];
                unsigned bl1 = Bpl[base + tg + 4][cn + g];
#pragma unroll
                for (int mt = 0; mt < 2; mt++) {
                    mma16(acc[mt][nt], ah[mt], bh0, bh1);
                    mma16(acc[mt][nt], al[mt], bh0, bh1);
                    mma16(acc[mt][nt], ah[mt], bl0, bl1);
                }
            }
        }
        __syncthreads();
    }

#pragma unroll
    for (int mt = 0; mt < 2; mt++) {
        int r0 = m0 + wm * 32 + mt * 16 + g;
        float bi0 = bias[r0], bi1 = bias[r0 + 8];
#pragma unroll
        for (int nt = 0; nt < 8; nt++) {
            int cn = n0 + wn * 64 + nt * 8 + 2 * tg;
            Yb[(size_t)r0 * SP + cn]           = acc[mt][nt][0] + bi0;
            Yb[(size_t)r0 * SP + cn + 1]       = acc[mt][nt][1] + bi0;
            Yb[(size_t)(r0 + 8) * SP + cn]     = acc[mt][nt][2] + bi1;
            Yb[(size_t)(r0 + 8) * SP + cn + 1] = acc[mt][nt][3] + bi1;
        }
    }
}

// ---------------------------------------------------------------------------
// Attention per (b,h). 3xBF16 both matmuls; P C-frag == A-frag (no shuffles).
// smem: Kh/Kl[128][36] (pairs along d) + Vh/Vl[64][72] (pairs along key)
//     = 73728 B dynamic
// ---------------------------------------------------------------------------
#define ATTN_SMEM ((2*128*36 + 2*64*72) * 4)

__device__ __forceinline__ size_t tok_off(int n, int hoff) {
    return (size_t)(n >> 1) * SP + ((n & 1) << 9) + hoff;
}

__global__ __launch_bounds__(256, 1)
void attn_kernel(const float* __restrict__ Q, const float* __restrict__ K,
                 const float* __restrict__ V, float* __restrict__ O)
{
    extern __shared__ unsigned smem_u[];
    unsigned (*Kph)[36] = reinterpret_cast<unsigned(*)[36]>(smem_u);
    unsigned (*Kpl)[36] = reinterpret_cast<unsigned(*)[36]>(smem_u + 128*36);
    unsigned (*Vph)[72] = reinterpret_cast<unsigned(*)[72]>(smem_u + 2*128*36);
    unsigned (*Vpl)[72] = reinterpret_cast<unsigned(*)[72]>(smem_u + 2*128*36 + 64*72);

    const int tid = threadIdx.x, lane = tid & 31, warp = tid >> 5;
    const int g = lane >> 2, tg = lane & 3;

    const int b = blockIdx.z, h = blockIdx.y;
    const int n0 = blockIdx.x * 128;
    const size_t bb = (size_t)b * PER_B;
    const int hoff = h * 64;

    // Q fragments rows warp*16+g, +8; k = d (4 chunks of 16); pre-scale 1/8
    const int r0l = warp * 16 + g, r1l = r0l + 8;
    const float* q0 = Q + bb + tok_off(n0 + r0l, hoff);
    const float* q1 = Q + bb + tok_off(n0 + r1l, hoff);
    unsigned qh[4][4], ql[4][4];
#pragma unroll
    for (int kc = 0; kc < 4; kc++) {
        int d0 = kc * 16 + 2 * tg;
        split2(q0[d0] * 0.125f,     q0[d0 + 1] * 0.125f, qh[kc][0], ql[kc][0]);
        split2(q1[d0] * 0.125f,     q1[d0 + 1] * 0.125f, qh[kc][1], ql[kc][1]);
        split2(q0[d0 + 8] * 0.125f, q0[d0 + 9] * 0.125f, qh[kc][2], ql[kc][2]);
        split2(q1[d0 + 8] * 0.125f, q1[d0 + 9] * 0.125f, qh[kc][3], ql[kc][3]);
    }

    float mr0 = -1e30f, mr1 = -1e30f, l0 = 0.f, l1 = 0.f;
    float oa[8][4];
#pragma unroll
    for (int dt = 0; dt < 8; dt++)
#pragma unroll
        for (int i = 0; i < 4; i++) oa[dt][i] = 0.f;

    for (int kb = 0; kb < 8; kb++) {
        // K tile: 128 keys x 64 d, pack pairs along d
#pragma unroll
        for (int i = 0; i < 8; i++) {
            int f = tid + i * 256;
            int r = f >> 4, c = (f & 15) << 2;
            size_t off = bb + tok_off(kb * 128 + r, hoff) + c;
            float4 kv = *reinterpret_cast<const float4*>(K + off);
            split2(kv.x, kv.y, Kph[r][c >> 1],       Kpl[r][c >> 1]);
            split2(kv.z, kv.w, Kph[r][(c >> 1) + 1], Kpl[r][(c >> 1) + 1]);
        }
        // V tile: pack pairs along key (keys 2pr, 2pr+1 = channel kb*64+pr,
        // spatial hoff and hoff+512)
#pragma unroll
        for (int i = 0; i < 8; i++) {
            int f = tid + i * 256;
            int pr = f >> 5, c = (f & 31) << 1;
            const float* vb = V + bb + (size_t)(kb * 64 + pr) * SP + hoff + c;
            float2 a = *reinterpret_cast<const float2*>(vb);
            float2 bq = *reinterpret_cast<const float2*>(vb + 512);
            split2(a.x, bq.x, Vph[pr][c],     Vpl[pr][c]);
            split2(a.y, bq.y, Vph[pr][c + 1], Vpl[pr][c + 1]);
        }
        __syncthreads();

        // S = Q K^T : 16 n-tiles x 4 k16 chunks, 3 mmas each
        float sc[16][4];
#pragma unroll
        for (int nt = 0; nt < 16; nt++) {
            sc[nt][0] = sc[nt][1] = sc[nt][2] = sc[nt][3] = 0.f;
#pragma unroll
            for (int kc = 0; kc < 4; kc++) {
                unsigned bh0 = Kph[nt * 8 + g][kc * 8 + tg];
                unsigned bh1 = Kph[nt * 8 + g][kc * 8 + tg + 4];
                unsigned bl0 = Kpl[nt * 8 + g][kc * 8 + tg];
                unsigned bl1 = Kpl[nt * 8 + g][kc * 8 + tg + 4];
                mma16(sc[nt], qh[kc], bh0, bh1);
                mma16(sc[nt], ql[kc], bh0, bh1);
                mma16(sc[nt], qh[kc], bl0, bl1);
            }
        }

        // online softmax (row g -> sc[..][0,1], row g+8 -> sc[..][2,3])
        float mx0 = -1e30f, mx1 = -1e30f;
#pragma unroll
        for (int nt = 0; nt < 16; nt++) {
            mx0 = fmaxf(mx0, fmaxf(sc[nt][0], sc[nt][1]));
            mx1 = fmaxf(mx1, fmaxf(sc[nt][2], sc[nt][3]));
        }
        mx0 = fmaxf(mx0, __shfl_xor_sync(0xffffffff, mx0, 1));
        mx0 = fmaxf(mx0, __shfl_xor_sync(0xffffffff, mx0, 2));
        mx1 = fmaxf(mx1, __shfl_xor_sync(0xffffffff, mx1, 1));
        mx1 = fmaxf(mx1, __shfl_xor_sync(0xffffffff, mx1, 2));
        float mn0 = fmaxf(mr0, mx0), mn1 = fmaxf(mr1, mx1);
        float al0 = __expf(mr0 - mn0), al1 = __expf(mr1 - mn1);
        float ps0 = 0.f, ps1 = 0.f;
#pragma unroll
        for (int nt = 0; nt < 16; nt++) {
            sc[nt][0] = __expf(sc[nt][0] - mn0);
            sc[nt][1] = __expf(sc[nt][1] - mn0);
            sc[nt][2] = __expf(sc[nt][2] - mn1);
            sc[nt][3] = __expf(sc[nt][3] - mn1);
            ps0 += sc[nt][0] + sc[nt][1];
            ps1 += sc[nt][2] + sc[nt][3];
        }
        ps0 += __shfl_xor_sync(0xffffffff, ps0, 1);
        ps0 += __shfl_xor_sync(0xffffffff, ps0, 2);
        ps1 += __shfl_xor_sync(0xffffffff, ps1, 1);
        ps1 += __shfl_xor_sync(0xffffffff, ps1, 2);
        l0 = l0 * al0 + ps0;
        l1 = l1 * al1 + ps1;
        mr0 = mn0; mr1 = mn1;
#pragma unroll
        for (int dt = 0; dt < 8; dt++) {
            oa[dt][0] *= al0; oa[dt][1] *= al0;
            oa[dt][2] *= al1; oa[dt][3] *= al1;
        }

        // O += P V : 8 key-chunks (k16) x 8 d-tiles; P A-frag direct from C-frags
#pragma unroll
        for (int nt2 = 0; nt2 < 8; nt2++) {
            const float* s0 = sc[2 * nt2];
            const float* s1 = sc[2 * nt2 + 1];
            unsigned pah[4], pal[4];
            split2(s0[0], s0[1], pah[0], pal[0]);
            split2(s0[2], s0[3], pah[1], pal[1]);
            split2(s1[0], s1[1], pah[2], pal[2]);
            split2(s1[2], s1[3], pah[3], pal[3]);
#pragma unroll
            for (int dt = 0; dt < 8; dt++) {
                unsigned bh0 = Vph[nt2 * 8 + tg][dt * 8 + g];
                unsigned bh1 = Vph[nt2 * 8 + tg + 4][dt * 8 + g];
                unsigned bl0 = Vpl[nt2 * 8 + tg][dt * 8 + g];
                unsigned bl1 = Vpl[nt2 * 8 + tg + 4][dt * 8 + g];
                mma16(oa[dt], pah, bh0, bh1);
                mma16(oa[dt], pal, bh0, bh1);
                mma16(oa[dt], pah, bl0, bl1);
            }
        }
        __syncthreads();
    }

    const float inv0 = 1.f / l0, inv1 = 1.f / l1;

    // transpose O through smem (reuse) for coalesced image store
    float (*Os)[68] = reinterpret_cast<float(*)[68]>(smem_u);
#pragma unroll
    for (int dt = 0; dt < 8; dt++) {
        Os[r0l][dt * 8 + 2 * tg]     = oa[dt][0] * inv0;
        Os[r0l][dt * 8 + 2 * tg + 1] = oa[dt][1] * inv0;
        Os[r1l][dt * 8 + 2 * tg]     = oa[dt][2] * inv1;
        Os[r1l][dt * 8 + 2 * tg + 1] = oa[dt][3] * inv1;
    }
    __syncthreads();
    for (int idx = tid; idx < 64 * 128; idx += 256) {
        int j = idx >> 7, nl = idx & 127;
        O[bb + (size_t)(hoff + j) * SP + n0 + nl] = Os[nl][j];
    }
}

// ---------------------------------------------------------------------------
// InstanceNorm per (b,c) row, in-place. biased var, eps=1e-5
// ---------------------------------------------------------------------------
__global__ __launch_bounds__(256)
void inorm_kernel(float* __restrict__ Y)
{
    float* p = Y + (size_t)blockIdx.x * SP;
    const int tid = threadIdx.x, lane = tid & 31, warp = tid >> 5;
    float4 v = reinterpret_cast<const float4*>(p)[tid];
    float s = v.x + v.y + v.z + v.w;
    float q = v.x * v.x + v.y * v.y + v.z * v.z + v.w * v.w;
#pragma unroll
    for (int off = 16; off > 0; off >>= 1) {
        s += __shfl_xor_sync(0xffffffff, s, off);
        q += __shfl_xor_sync(0xffffffff, q, off);
    }
    __shared__ float ss[8], sq[8];
    if (lane == 0) { ss[warp] = s; sq[warp] = q; }
    __syncthreads();
    __shared__ float fmean, finv;
    if (tid == 0) {
        float S = 0.f, Qs = 0.f;
#pragma unroll
        for (int i = 0; i < 8; i++) { S += ss[i]; Qs += sq[i]; }
        float mean = S * (1.f / SP);
        float var = Qs * (1.f / SP) - mean * mean;
        fmean = mean;
        finv = rsqrtf(var + 1e-5f);
    }
    __syncthreads();
    float mean = fmean, inv = finv;
    v.x = (v.x - mean) * inv;
    v.y = (v.y - mean) * inv;
    v.z = (v.z - mean) * inv;
    v.w = (v.w - mean) * inv;
    reinterpret_cast<float4*>(p)[tid] = v;
}

// ---------------------------------------------------------------------------
extern "C" void kernel_launch(void* const* d_in, const int* in_sizes, int n_in,
                              void* d_out, int out_size)
{
    const float* x  = (const float*)d_in[0];
    const float* Wq = (const float*)d_in[1];
    const float* bq = (const float*)d_in[2];
    const float* Wk = (const float*)d_in[3];
    const float* bk = (const float*)d_in[4];
    const float* Wv = (const float*)d_in[5];
    const float* bv = (const float*)d_in[6];
    const float* Wo = (const float*)d_in[7];
    const float* bo = (const float*)d_in[8];

    float *gq, *gk, *gv, *gatt, *go1;
    cudaGetSymbolAddress((void**)&gq, g_q);
    cudaGetSymbolAddress((void**)&gk, g_k);
    cudaGetSymbolAddress((void**)&gv, g_v);
    cudaGetSymbolAddress((void**)&gatt, g_att);
    cudaGetSymbolAddress((void**)&go1, g_o1);

    cudaFuncSetAttribute(gemm512_kernel, cudaFuncAttributeMaxDynamicSharedMemorySize, GEMM_SMEM);
    cudaFuncSetAttribute(attn_kernel,    cudaFuncAttributeMaxDynamicSharedMemorySize, ATTN_SMEM);

    dim3 gg(8, 4, BATCH), bt(256);
    gemm512_kernel<<<gg, bt, GEMM_SMEM>>>(Wq, bq, x, gq);
    gemm512_kernel<<<gg, bt, GEMM_SMEM>>>(Wk, bk, x, gk);
    gemm512_kernel<<<gg, bt, GEMM_SMEM>>>(Wv, bv, x, gv);

    attn_kernel<<<dim3(8, NHEAD, BATCH), bt, ATTN_SMEM>>>(gq, gk, gv, gatt);

    gemm512_kernel<<<gg, bt, GEMM_SMEM>>>(Wo, bo, gatt, go1);
    inorm_kernel<<<BATCH * CH, 256>>>(go1);
    gemm512_kernel<<<gg, bt, GEMM_SMEM>>>(Wo, bo, go1, (float*)d_out);
}

// round 7
// speedup vs baseline: 1.7429x; 1.0296x over previous
#include <cuda_runtime.h>
#include <cuda_bf16.h>
#include <cstdint>

// ---------------------------------------------------------------------------
// B=16, C=512, S=1024, HEAD=8, D_K=64
// heads view: token n -> channel n>>1, feature j=h*64+d -> spatial ((n&1)<<9)+j
// 3xBF16 compensated: x = hi + lo (bf16 each), A*B ~= Ah*Bh + Al*Bh + Ah*Bl
// MMA loops ordered for independent accumulator chains (distance >= 8).
// ---------------------------------------------------------------------------
#define BATCH   16
#define CH      512
#define SP      1024
#define NHEAD   8
#define PER_B   (CH*SP)

__device__ float g_q[BATCH*PER_B];
__device__ float g_k[BATCH*PER_B];
__device__ float g_v[BATCH*PER_B];
__device__ float g_att[BATCH*PER_B];
__device__ float g_o1[BATCH*PER_B];

__device__ __forceinline__ unsigned packbf(float a, float b) {
    unsigned r;
    asm("cvt.rn.bf16x2.f32 %0, %1, %2;" : "=r"(r) : "f"(b), "f"(a));
    return r;
}
__device__ __forceinline__ void split2(float a, float b, unsigned& hi, unsigned& lo) {
    hi = packbf(a, b);
    float ha = __uint_as_float(hi << 16);
    float hb = __uint_as_float(hi & 0xffff0000u);
    lo = packbf(a - ha, b - hb);
}
__device__ __forceinline__ void mma16(float* c, const unsigned* a, unsigned b0, unsigned b1) {
    asm volatile(
        "mma.sync.aligned.m16n8k16.row.col.f32.bf16.bf16.f32 "
        "{%0,%1,%2,%3},{%4,%5,%6,%7},{%8,%9},{%0,%1,%2,%3};"
        : "+f"(c[0]), "+f"(c[1]), "+f"(c[2]), "+f"(c[3])
        : "r"(a[0]), "r"(a[1]), "r"(a[2]), "r"(a[3]), "r"(b0), "r"(b1));
}

// ---------------------------------------------------------------------------
// GEMM body: Y[b](128x1024 slice) = W[512x512] @ X[b] + bias, 3xBF16.
// 256 thr. Warp grid 4(m) x 2(n); warp tile 32x64.
// smem (bf16x2 pairs): Ah/Al[128][20], Bh/Bl[16][132] = 37376 B
// ---------------------------------------------------------------------------
#define GEMM_SMEM ((2*128*20 + 2*16*132) * 4)

__device__ __forceinline__ void gemm_body(
    const float* __restrict__ W, const float* __restrict__ bias,
    const float* __restrict__ Xb, float* __restrict__ Yb,
    int m0, int n0, unsigned* gsm)
{
    unsigned (*Ahp)[20]  = reinterpret_cast<unsigned(*)[20]>(gsm);
    unsigned (*Alp)[20]  = reinterpret_cast<unsigned(*)[20]>(gsm + 128*20);
    unsigned (*Bph)[132] = reinterpret_cast<unsigned(*)[132]>(gsm + 2*128*20);
    unsigned (*Bpl)[132] = reinterpret_cast<unsigned(*)[132]>(gsm + 2*128*20 + 16*132);

    const int tid = threadIdx.x, lane = tid & 31, warp = tid >> 5;
    const int wm = warp & 3, wn = warp >> 2;
    const int g = lane >> 2, tg = lane & 3;

    float acc[2][8][4];
#pragma unroll
    for (int mt = 0; mt < 2; mt++)
#pragma unroll
        for (int nt = 0; nt < 8; nt++)
#pragma unroll
            for (int i = 0; i < 4; i++) acc[mt][nt][i] = 0.f;

    for (int k0 = 0; k0 < 512; k0 += 32) {
#pragma unroll
        for (int i = 0; i < 4; i++) {
            int f = tid + i * 256;
            int r = f >> 3, c = (f & 7) << 2;
            float4 v = *reinterpret_cast<const float4*>(W + (size_t)(m0 + r) * 512 + k0 + c);
            split2(v.x, v.y, Ahp[r][c >> 1],       Alp[r][c >> 1]);
            split2(v.z, v.w, Ahp[r][(c >> 1) + 1], Alp[r][(c >> 1) + 1]);
        }
#pragma unroll
        for (int i = 0; i < 2; i++) {
            int idx = tid + i * 256;
            int pr = idx >> 5, c = (idx & 31) << 2;
            const float* base = Xb + (size_t)(k0 + 2 * pr) * SP + n0 + c;
            float4 r0 = *reinterpret_cast<const float4*>(base);
            float4 r1 = *reinterpret_cast<const float4*>(base + SP);
            split2(r0.x, r1.x, Bph[pr][c],     Bpl[pr][c]);
            split2(r0.y, r1.y, Bph[pr][c + 1], Bpl[pr][c + 1]);
            split2(r0.z, r1.z, Bph[pr][c + 2], Bpl[pr][c + 2]);
            split2(r0.w, r1.w, Bph[pr][c + 3], Bpl[pr][c + 3]);
        }
        __syncthreads();

#pragma unroll
        for (int kc = 0; kc < 2; kc++) {
            const int base = kc * 8;
            unsigned ah[2][4], al[2][4];
#pragma unroll
            for (int mt = 0; mt < 2; mt++) {
                int rm = wm * 32 + mt * 16;
                ah[mt][0] = Ahp[rm + g][base + tg];
                ah[mt][1] = Ahp[rm + g + 8][base + tg];
                ah[mt][2] = Ahp[rm + g][base + tg + 4];
                ah[mt][3] = Ahp[rm + g + 8][base + tg + 4];
                al[mt][0] = Alp[rm + g][base + tg];
                al[mt][1] = Alp[rm + g + 8][base + tg];
                al[mt][2] = Alp[rm + g][base + tg + 4];
                al[mt][3] = Alp[rm + g + 8][base + tg + 4];
            }
#pragma unroll
            for (int ntc = 0; ntc < 2; ntc++) {
                unsigned bh0[4], bh1[4], bl0[4], bl1[4];
#pragma unroll
                for (int j = 0; j < 4; j++) {
                    int cn = wn * 64 + (ntc * 4 + j) * 8;
                    bh0[j] = Bph[base + tg][cn + g];
                    bh1[j] = Bph[base + tg + 4][cn + g];
                    bl0[j] = Bpl[base + tg][cn + g];
                    bl1[j] = Bpl[base + tg + 4][cn + g];
                }
                // term-ordered passes: dependency distance 8
#pragma unroll
                for (int j = 0; j < 4; j++) {
                    mma16(acc[0][ntc * 4 + j], ah[0], bh0[j], bh1[j]);
                    mma16(acc[1][ntc * 4 + j], ah[1], bh0[j], bh1[j]);
                }
#pragma unroll
                for (int j = 0; j < 4; j++) {
                    mma16(acc[0][ntc * 4 + j], al[0], bh0[j], bh1[j]);
                    mma16(acc[1][ntc * 4 + j], al[1], bh0[j], bh1[j]);
                }
#pragma unroll
                for (int j = 0; j < 4; j++) {
                    mma16(acc[0][ntc * 4 + j], ah[0], bl0[j], bl1[j]);
                    mma16(acc[1][ntc * 4 + j], ah[1], bl0[j], bl1[j]);
                }
            }
        }
        __syncthreads();
    }

#pragma unroll
    for (int mt = 0; mt < 2; mt++) {
        int r0 = m0 + wm * 32 + mt * 16 + g;
        float bi0 = bias[r0], bi1 = bias[r0 + 8];
#pragma unroll
        for (int nt = 0; nt < 8; nt++) {
            int cn = n0 + wn * 64 + nt * 8 + 2 * tg;
            Yb[(size_t)r0 * SP + cn]           = acc[mt][nt][0] + bi0;
            Yb[(size_t)r0 * SP + cn + 1]       = acc[mt][nt][1] + bi0;
            Yb[(size_t)(r0 + 8) * SP + cn]     = acc[mt][nt][2] + bi1;
            Yb[(size_t)(r0 + 8) * SP + cn + 1] = acc[mt][nt][3] + bi1;
        }
    }
}

// fused QKV: grid (8, 12, 16); y>>2 selects {Q,K,V}
__global__ __launch_bounds__(256, 2)
void qkv_kernel(const float* __restrict__ X,
                const float* __restrict__ Wq, const float* __restrict__ bq,
                const float* __restrict__ Wk, const float* __restrict__ bk,
                const float* __restrict__ Wv, const float* __restrict__ bv,
                float* __restrict__ Yq, float* __restrict__ Yk, float* __restrict__ Yv)
{
    extern __shared__ unsigned gsm[];
    const int sel = blockIdx.y >> 2;
    const int m0 = (blockIdx.y & 3) * 128;
    const int n0 = blockIdx.x * 128;
    const float* Xb = X + (size_t)blockIdx.z * PER_B;
    const float* W  = sel == 0 ? Wq : (sel == 1 ? Wk : Wv);
    const float* bi = sel == 0 ? bq : (sel == 1 ? bk : bv);
    float* Y = (sel == 0 ? Yq : (sel == 1 ? Yk : Yv)) + (size_t)blockIdx.z * PER_B;
    gemm_body(W, bi, Xb, Y, m0, n0, gsm);
}

__global__ __launch_bounds__(256, 2)
void gemm512_kernel(const float* __restrict__ W, const float* __restrict__ bias,
                    const float* __restrict__ X, float* __restrict__ Y)
{
    extern __shared__ unsigned gsm[];
    gemm_body(W, bias, X + (size_t)blockIdx.z * PER_B, Y + (size_t)blockIdx.z * PER_B,
              blockIdx.y * 128, blockIdx.x * 128, gsm);
}

// ---------------------------------------------------------------------------
// Attention per (b,h). 3xBF16; P C-frag == A-frag. ILP-ordered MMA passes.
// smem: Kh/Kl[128][36] + Vh/Vl[64][72] = 73728 B dynamic
// ---------------------------------------------------------------------------
#define ATTN_SMEM ((2*128*36 + 2*64*72) * 4)

__device__ __forceinline__ size_t tok_off(int n, int hoff) {
    return (size_t)(n >> 1) * SP + ((n & 1) << 9) + hoff;
}

__global__ __launch_bounds__(256, 1)
void attn_kernel(const float* __restrict__ Q, const float* __restrict__ K,
                 const float* __restrict__ V, float* __restrict__ O)
{
    extern __shared__ unsigned smem_u[];
    unsigned (*Kph)[36] = reinterpret_cast<unsigned(*)[36]>(smem_u);
    unsigned (*Kpl)[36] = reinterpret_cast<unsigned(*)[36]>(smem_u + 128*36);
    unsigned (*Vph)[72] = reinterpret_cast<unsigned(*)[72]>(smem_u + 2*128*36);
    unsigned (*Vpl)[72] = reinterpret_cast<unsigned(*)[72]>(smem_u + 2*128*36 + 64*72);

    const int tid = threadIdx.x, lane = tid & 31, warp = tid >> 5;
    const int g = lane >> 2, tg = lane & 3;

    const int b = blockIdx.z, h = blockIdx.y;
    const int n0 = blockIdx.x * 128;
    const size_t bb = (size_t)b * PER_B;
    const int hoff = h * 64;

    const int r0l = warp * 16 + g, r1l = r0l + 8;
    const float* q0 = Q + bb + tok_off(n0 + r0l, hoff);
    const float* q1 = Q + bb + tok_off(n0 + r1l, hoff);
    unsigned qh[4][4], ql[4][4];
#pragma unroll
    for (int kc = 0; kc < 4; kc++) {
        int d0 = kc * 16 + 2 * tg;
        split2(q0[d0] * 0.125f,     q0[d0 + 1] * 0.125f, qh[kc][0], ql[kc][0]);
        split2(q1[d0] * 0.125f,     q1[d0 + 1] * 0.125f, qh[kc][1], ql[kc][1]);
        split2(q0[d0 + 8] * 0.125f, q0[d0 + 9] * 0.125f, qh[kc][2], ql[kc][2]);
        split2(q1[d0 + 8] * 0.125f, q1[d0 + 9] * 0.125f, qh[kc][3], ql[kc][3]);
    }

    float mr0 = -1e30f, mr1 = -1e30f, l0 = 0.f, l1 = 0.f;
    float oa[8][4];
#pragma unroll
    for (int dt = 0; dt < 8; dt++)
#pragma unroll
        for (int i = 0; i < 4; i++) oa[dt][i] = 0.f;

    for (int kb = 0; kb < 8; kb++) {
#pragma unroll
        for (int i = 0; i < 8; i++) {
            int f = tid + i * 256;
            int r = f >> 4, c = (f & 15) << 2;
            size_t off = bb + tok_off(kb * 128 + r, hoff) + c;
            float4 kv = *reinterpret_cast<const float4*>(K + off);
            split2(kv.x, kv.y, Kph[r][c >> 1],       Kpl[r][c >> 1]);
            split2(kv.z, kv.w, Kph[r][(c >> 1) + 1], Kpl[r][(c >> 1) + 1]);
        }
#pragma unroll
        for (int i = 0; i < 8; i++) {
            int f = tid + i * 256;
            int pr = f >> 5, c = (f & 31) << 1;
            const float* vb = V + bb + (size_t)(kb * 64 + pr) * SP + hoff + c;
            float2 a = *reinterpret_cast<const float2*>(vb);
            float2 bq = *reinterpret_cast<const float2*>(vb + 512);
            split2(a.x, bq.x, Vph[pr][c],     Vpl[pr][c]);
            split2(a.y, bq.y, Vph[pr][c + 1], Vpl[pr][c + 1]);
        }
        __syncthreads();

        // S = Q K^T : kc outer, nt chunks of 8, term-ordered passes
        float sc[16][4];
#pragma unroll
        for (int nt = 0; nt < 16; nt++) {
            sc[nt][0] = sc[nt][1] = sc[nt][2] = sc[nt][3] = 0.f;
        }
#pragma unroll
        for (int kc = 0; kc < 4; kc++) {
#pragma unroll
            for (int half = 0; half < 2; half++) {
                unsigned kh0[8], kh1[8], kl0[8], kl1[8];
#pragma unroll
                for (int j = 0; j < 8; j++) {
                    int nt = half * 8 + j;
                    kh0[j] = Kph[nt * 8 + g][kc * 8 + tg];
                    kh1[j] = Kph[nt * 8 + g][kc * 8 + tg + 4];
                    kl0[j] = Kpl[nt * 8 + g][kc * 8 + tg];
                    kl1[j] = Kpl[nt * 8 + g][kc * 8 + tg + 4];
                }
#pragma unroll
                for (int j = 0; j < 8; j++)
                    mma16(sc[half * 8 + j], qh[kc], kh0[j], kh1[j]);
#pragma unroll
                for (int j = 0; j < 8; j++)
                    mma16(sc[half * 8 + j], ql[kc], kh0[j], kh1[j]);
#pragma unroll
                for (int j = 0; j < 8; j++)
                    mma16(sc[half * 8 + j], qh[kc], kl0[j], kl1[j]);
            }
        }

        // online softmax
        float mx0 = -1e30f, mx1 = -1e30f;
#pragma unroll
        for (int nt = 0; nt < 16; nt++) {
            mx0 = fmaxf(mx0, fmaxf(sc[nt][0], sc[nt][1]));
            mx1 = fmaxf(mx1, fmaxf(sc[nt][2], sc[nt][3]));
        }
        mx0 = fmaxf(mx0, __shfl_xor_sync(0xffffffff, mx0, 1));
        mx0 = fmaxf(mx0, __shfl_xor_sync(0xffffffff, mx0, 2));
        mx1 = fmaxf(mx1, __shfl_xor_sync(0xffffffff, mx1, 1));
        mx1 = fmaxf(mx1, __shfl_xor_sync(0xffffffff, mx1, 2));
        float mn0 = fmaxf(mr0, mx0), mn1 = fmaxf(mr1, mx1);
        float al0 = __expf(mr0 - mn0), al1 = __expf(mr1 - mn1);
        float ps0 = 0.f, ps1 = 0.f;
#pragma unroll
        for (int nt = 0; nt < 16; nt++) {
            sc[nt][0] = __expf(sc[nt][0] - mn0);
            sc[nt][1] = __expf(sc[nt][1] - mn0);
            sc[nt][2] = __expf(sc[nt][2] - mn1);
            sc[nt][3] = __expf(sc[nt][3] - mn1);
            ps0 += sc[nt][0] + sc[nt][1];
            ps1 += sc[nt][2] + sc[nt][3];
        }
        ps0 += __shfl_xor_sync(0xffffffff, ps0, 1);
        ps0 += __shfl_xor_sync(0xffffffff, ps0, 2);
        ps1 += __shfl_xor_sync(0xffffffff, ps1, 1);
        ps1 += __shfl_xor_sync(0xffffffff, ps1, 2);
        l0 = l0 * al0 + ps0;
        l1 = l1 * al1 + ps1;
        mr0 = mn0; mr1 = mn1;
#pragma unroll
        for (int dt = 0; dt < 8; dt++) {
            oa[dt][0] *= al0; oa[dt][1] *= al0;
            oa[dt][2] *= al1; oa[dt][3] *= al1;
        }

        // O += P V : per key-chunk, V-frags for all 8 d-tiles, term passes
#pragma unroll
        for (int nt2 = 0; nt2 < 8; nt2++) {
            const float* s0 = sc[2 * nt2];
            const float* s1 = sc[2 * nt2 + 1];
            unsigned pah[4], pal[4];
            split2(s0[0], s0[1], pah[0], pal[0]);
            split2(s0[2], s0[3], pah[1], pal[1]);
            split2(s1[0], s1[1], pah[2], pal[2]);
            split2(s1[2], s1[3], pah[3], pal[3]);
            unsigned vh0[8], vh1[8], vl0[8], vl1[8];
#pragma unroll
            for (int dt = 0; dt < 8; dt++) {
                vh0[dt] = Vph[nt2 * 8 + tg][dt * 8 + g];
                vh1[dt] = Vph[nt2 * 8 + tg + 4][dt * 8 + g];
                vl0[dt] = Vpl[nt2 * 8 + tg][dt * 8 + g];
                vl1[dt] = Vpl[nt2 * 8 + tg + 4][dt * 8 + g];
            }
#pragma unroll
            for (int dt = 0; dt < 8; dt++)
                mma16(oa[dt], pah, vh0[dt], vh1[dt]);
#pragma unroll
            for (int dt = 0; dt < 8; dt++)
                mma16(oa[dt], pal, vh0[dt], vh1[dt]);
#pragma unroll
            for (int dt = 0; dt < 8; dt++)
                mma16(oa[dt], pah, vl0[dt], vl1[dt]);
        }
        __syncthreads();
    }

    const float inv0 = 1.f / l0, inv1 = 1.f / l1;

    float (*Os)[68] = reinterpret_cast<float(*)[68]>(smem_u);
#pragma unroll
    for (int dt = 0; dt < 8; dt++) {
        Os[r0l][dt * 8 + 2 * tg]     = oa[dt][0] * inv0;
        Os[r0l][dt * 8 + 2 * tg + 1] = oa[dt][1] * inv0;
        Os[r1l][dt * 8 + 2 * tg]     = oa[dt][2] * inv1;
        Os[r1l][dt * 8 + 2 * tg + 1] = oa[dt][3] * inv1;
    }
    __syncthreads();
    for (int idx = tid; idx < 64 * 128; idx += 256) {
        int j = idx >> 7, nl = idx & 127;
        O[bb + (size_t)(hoff + j) * SP + n0 + nl] = Os[nl][j];
    }
}

// ---------------------------------------------------------------------------
// InstanceNorm per (b,c) row, in-place. biased var, eps=1e-5
// ---------------------------------------------------------------------------
__global__ __launch_bounds__(256)
void inorm_kernel(float* __restrict__ Y)
{
    float* p = Y + (size_t)blockIdx.x * SP;
    const int tid = threadIdx.x, lane = tid & 31, warp = tid >> 5;
    float4 v = reinterpret_cast<const float4*>(p)[tid];
    float s = v.x + v.y + v.z + v.w;
    float q = v.x * v.x + v.y * v.y + v.z * v.z + v.w * v.w;
#pragma unroll
    for (int off = 16; off > 0; off >>= 1) {
        s += __shfl_xor_sync(0xffffffff, s, off);
        q += __shfl_xor_sync(0xffffffff, q, off);
    }
    __shared__ float ss[8], sq[8];
    if (lane == 0) { ss[warp] = s; sq[warp] = q; }
    __syncthreads();
    __shared__ float fmean, finv;
    if (tid == 0) {
        float S = 0.f, Qs = 0.f;
#pragma unroll
        for (int i = 0; i < 8; i++) { S += ss[i]; Qs += sq[i]; }
        float mean = S * (1.f / SP);
        float var = Qs * (1.f / SP) - mean * mean;
        fmean = mean;
        finv = rsqrtf(var + 1e-5f);
    }
    __syncthreads();
    float mean = fmean, inv = finv;
    v.x = (v.x - mean) * inv;
    v.y = (v.y - mean) * inv;
    v.z = (v.z - mean) * inv;
    v.w = (v.w - mean) * inv;
    reinterpret_cast<float4*>(p)[tid] = v;
}

// ---------------------------------------------------------------------------
extern "C" void kernel_launch(void* const* d_in, const int* in_sizes, int n_in,
                              void* d_out, int out_size)
{
    const float* x  = (const float*)d_in[0];
    const float* Wq = (const float*)d_in[1];
    const float* bq = (const float*)d_in[2];
    const float* Wk = (const float*)d_in[3];
    const float* bk = (const float*)d_in[4];
    const float* Wv = (const float*)d_in[5];
    const float* bv = (const float*)d_in[6];
    const float* Wo = (const float*)d_in[7];
    const float* bo = (const float*)d_in[8];

    float *gq, *gk, *gv, *gatt, *go1;
    cudaGetSymbolAddress((void**)&gq, g_q);
    cudaGetSymbolAddress((void**)&gk, g_k);
    cudaGetSymbolAddress((void**)&gv, g_v);
    cudaGetSymbolAddress((void**)&gatt, g_att);
    cudaGetSymbolAddress((void**)&go1, g_o1);

    cudaFuncSetAttribute(qkv_kernel,     cudaFuncAttributeMaxDynamicSharedMemorySize, GEMM_SMEM);
    cudaFuncSetAttribute(gemm512_kernel, cudaFuncAttributeMaxDynamicSharedMemorySize, GEMM_SMEM);
    cudaFuncSetAttribute(attn_kernel,    cudaFuncAttributeMaxDynamicSharedMemorySize, ATTN_SMEM);

    dim3 bt(256);
    qkv_kernel<<<dim3(8, 12, BATCH), bt, GEMM_SMEM>>>(x, Wq, bq, Wk, bk, Wv, bv, gq, gk, gv);

    attn_kernel<<<dim3(8, NHEAD, BATCH), bt, ATTN_SMEM>>>(gq, gk, gv, gatt);

    gemm512_kernel<<<dim3(8, 4, BATCH), bt, GEMM_SMEM>>>(Wo, bo, gatt, go1);
    inorm_kernel<<<BATCH * CH, 256>>>(go1);
    gemm512_kernel<<<dim3(8, 4, BATCH), bt, GEMM_SMEM>>>(Wo, bo, go1, (float*)d_out);
}